// round 4
// baseline (speedup 1.0000x reference)
#include <cuda_runtime.h>

#define NTOK 512
#define DSTATE 192
#define HID 512
#define EMB 1024
#define NEMB 32
#define KC 256
#define HSS 36   // smem row stride (floats): 144 B rows, 16B-aligned

// scratch (allocs forbidden -> device globals)
__device__ int g_start[NEMB + 1];
__device__ int g_tokens[NTOK];
__device__ float g_H[NTOK * 4 * HID]; // [slot][m][HID], grouped slot order

struct Params {
    const float* W1[4];
    const float* b1[4];
    const float* W2[4];
    const float* b2[4];
    const float* te[4];
};

// ---------------------------------------------------------------------------
// Stage 1 (fused grouping): each block re-derives the token grouping from the
// raw ids (cheap, L2-resident), block 0 publishes it for stage 2, then the
// block computes H[slot][m][:] = relu(x_m . W1_m[e] + b1_m[e]).
// Grid: 128 blocks = (e,m), 512 threads = one HID column each.
// ---------------------------------------------------------------------------
template <int L, int OFF>
__device__ __forceinline__ void mlp1(const float* __restrict__ state,
                                     const float* __restrict__ W1,
                                     float b, int m, int s0, int n,
                                     const int* __restrict__ s_tokens,
                                     float* __restrict__ xs) {
    int j = threadIdx.x;
    for (int cb = 0; cb < n; cb += 16) {
        int rem = min(n - cb, 16);
        __syncthreads();
        for (int idx = j; idx < 16 * L; idx += 512) {
            int tk = idx / L, l = idx % L;
            float v = 0.f;
            if (tk < rem) {
                int tok = s_tokens[s0 + cb + tk];
                v = state[tok * DSTATE + OFF + l];
            }
            xs[tk * L + l] = v;
        }
        __syncthreads();

        float acc[16];
        #pragma unroll
        for (int t = 0; t < 16; t++) acc[t] = b;

        #pragma unroll 1
        for (int l0 = 0; l0 < L; l0 += 8) {
            float w[8];
            #pragma unroll
            for (int u = 0; u < 8; u++)
                w[u] = W1[(l0 + u) * HID + j];
            #pragma unroll
            for (int u = 0; u < 8; u++) {
                #pragma unroll
                for (int t = 0; t < 16; t++)
                    acc[t] = fmaf(xs[t * L + l0 + u], w[u], acc[t]);
            }
        }

        #pragma unroll
        for (int t = 0; t < 16; t++) {
            if (t < rem)
                g_H[((size_t)(s0 + cb + t) * 4 + m) * HID + j] = fmaxf(acc[t], 0.f);
        }
        __syncthreads();
    }
}

__global__ void __launch_bounds__(512) k_stage1(const float* __restrict__ state,
                                                const int* __restrict__ ids_raw,
                                                Params p) {
    __shared__ int s_cnt[NEMB];
    __shared__ int s_pos[NEMB];
    __shared__ int s_startA[NEMB + 1];
    __shared__ int s_tokens[NTOK];
    __shared__ int s_i64;
    __shared__ float xs[16 * 64];

    int tid = threadIdx.x; // 512

    // ---- in-block grouping (identical in every block; deterministic enough:
    //      slot ORDER may differ between blocks, but stage1 only uses its own
    //      (s0,n) range and token list, and all blocks compute the same counts;
    //      g_tokens/g_start published by block 0 are what stage2 consumes, and
    //      stage1's H writes are slot-addressed by ITS OWN scatter... so order
    //      MUST match block 0. Make scatter deterministic: slot by stable rank.
    if (tid < NEMB) s_cnt[tid] = 0;
    if (tid == 0) s_i64 = 1;
    __syncthreads();
    if (tid < 256 && ids_raw[2 * tid + 1] != 0) s_i64 = 0;
    __syncthreads();
    int myc = s_i64 ? ids_raw[2 * tid] : ids_raw[tid];
    atomicAdd(&s_cnt[myc], 1);
    __syncthreads();
    if (tid <= NEMB) {
        int s = 0;
        for (int jj = 0; jj < tid && jj < NEMB; jj++) s += s_cnt[jj];
        s_startA[tid] = s;
        if (tid < NEMB) s_pos[tid] = s;
    }
    __syncthreads();
    // deterministic scatter: token t gets rank = #earlier tokens with same id.
    // Serialize per-id via atomic in token order is NOT deterministic; instead
    // compute rank by scanning (cheap: each thread counts matches before it
    // among 512 ids -> 512 reads from smem ids). Stash ids in s_tokens first.
    s_tokens[tid] = myc;
    __syncthreads();
    int rank = 0;
    for (int t = 0; t < NTOK; t++) {
        int c2 = s_tokens[t];
        if (t < tid && c2 == myc) rank++;
    }
    __syncthreads();
    int slot = s_startA[myc] + rank;
    s_tokens[slot] = tid;
    __syncthreads();

    if (blockIdx.x == 0) {
        if (tid <= NEMB) g_start[tid] = s_startA[tid];
        g_tokens[tid] = s_tokens[tid];
    }

    // ---- per-block MLP
    int m = blockIdx.x & 3;
    int e = blockIdx.x >> 2;
    int s0 = s_startA[e];
    int n  = s_startA[e + 1] - s0;
    if (n == 0) return;

    float b;
    switch (m) {
        case 0: b = p.b1[0][e * HID + tid];
                mlp1<64, 0  >(state, p.W1[0] + (size_t)e * 64 * HID, b, 0, s0, n, s_tokens, xs); break;
        case 1: b = p.b1[1][e * HID + tid];
                mlp1<64, 64 >(state, p.W1[1] + (size_t)e * 64 * HID, b, 1, s0, n, s_tokens, xs); break;
        case 2: b = p.b1[2][e * HID + tid];
                mlp1<32, 128>(state, p.W1[2] + (size_t)e * 32 * HID, b, 2, s0, n, s_tokens, xs); break;
        case 3: b = p.b1[3][e * HID + tid];
                mlp1<32, 160>(state, p.W1[3] + (size_t)e * 32 * HID, b, 3, s0, n, s_tokens, xs); break;
    }
}

// ---------------------------------------------------------------------------
// Kernel 2: out = H . W2[e] + b2[e] + te.  (unchanged from round 3)
// ---------------------------------------------------------------------------
__device__ __forceinline__ void fma2(unsigned long long& acc,
                                     unsigned long long h2,
                                     unsigned long long w2) {
    asm("fma.rn.f32x2 %0, %1, %2, %0;" : "+l"(acc) : "l"(h2), "l"(w2));
}

template <int P>  // P even, 2..16: token pairs in flight
__device__ __forceinline__ void run_chunk(
    float* hs, const float* __restrict__ W2ec, const float* __restrict__ Hme,
    float init, int s0cb, int rem, int tid, int m, int c,
    float* __restrict__ out)
{
    constexpr int D = (P <= 8) ? 16 : 8;  // prefetch depth (reg-pressure tradeoff)

    unsigned long long acc[P];
    unsigned long long ivl;
    asm("mov.b64 %0, {%1,%1};" : "=l"(ivl) : "r"(__float_as_uint(init)));
    #pragma unroll
    for (int p = 0; p < P; p++) acc[p] = ivl;

    for (int kc = 0; kc < HID; kc += KC) {
        __syncthreads();
        // stage h transposed: hs[kk*HSS + tk], tk in [0, 2P)
        #pragma unroll
        for (int tk = 0; tk < 2 * P; tk++) {
            int slot = min(s0cb + tk, NTOK - 1); // clamp pad (discarded later)
            const float* src = Hme + (size_t)slot * (4 * HID) + kc;
            #pragma unroll
            for (int kk = 0; kk < KC; kk += 128)
                hs[(kk + tid) * HSS + tk] = src[kk + tid];
        }
        __syncthreads();

        const float* wp = W2ec + (size_t)kc * EMB;
        #pragma unroll 1
        for (int g = 0; g < KC; g += D) {
            // front-batch D independent streaming loads -> D lines in flight
            float w[D];
            #pragma unroll
            for (int j = 0; j < D; j++)
                w[j] = __ldcs(wp + (size_t)(g + j) * EMB);

            #pragma unroll
            for (int j = 0; j < D; j++) {
                unsigned long long w2;
                asm("mov.b64 %0, {%1,%1};" : "=l"(w2) : "r"(__float_as_uint(w[j])));
                const float* hrow = hs + (g + j) * HSS;
                #pragma unroll
                for (int p2 = 0; p2 < P / 2; p2++) {
                    ulonglong2 hv = *(const ulonglong2*)(hrow + 4 * p2); // LDS.128 bcast
                    fma2(acc[2 * p2],     hv.x, w2);
                    fma2(acc[2 * p2 + 1], hv.y, w2);
                }
            }
        }
    }

    #pragma unroll
    for (int p = 0; p < P; p++) {
        float2 v = *(float2*)&acc[p];
        int t0 = 2 * p;
        if (t0 < rem) {
            int tok = g_tokens[s0cb + t0];
            out[((size_t)tok * 4 + m) * EMB + c] = v.x;
        }
        if (t0 + 1 < rem) {
            int tok = g_tokens[s0cb + t0 + 1];
            out[((size_t)tok * 4 + m) * EMB + c] = v.y;
        }
    }
}

__global__ void __launch_bounds__(128) k_stage2(Params p, float* __restrict__ out) {
    int tile = blockIdx.x; // 0..7 (128 cols each)
    int m    = blockIdx.y; // 0..3
    int e    = blockIdx.z; // 0..31
    int s0 = g_start[e];
    int n  = g_start[e + 1] - s0;
    if (n == 0) return;

    int tid = threadIdx.x;
    int c = tile * 128 + tid;
    const float* __restrict__ W2ec = p.W2[m] + (size_t)e * HID * EMB + c;
    const float* __restrict__ Hme  = g_H + m * HID;
    float init = p.b2[m][e * EMB + c] + p.te[m][c];

    __shared__ __align__(16) float hs[KC * HSS];

    for (int cb = 0; cb < n; cb += 32) {
        int rem = min(n - cb, 32);
        int pairsEven = ((rem + 3) >> 2) << 1; // ceil(rem/2) rounded up to even
        int s0cb = s0 + cb;
        switch (pairsEven) {
#define CASE(PP) case PP: run_chunk<PP>(hs, W2ec, Hme, init, s0cb, rem, tid, m, c, out); break;
            CASE(2) CASE(4) CASE(6) CASE(8) CASE(10) CASE(12) CASE(14) CASE(16)
#undef CASE
        }
    }
}

// ---------------------------------------------------------------------------
extern "C" void kernel_launch(void* const* d_in, const int* in_sizes, int n_in,
                              void* d_out, int out_size) {
    const float* state = (const float*)d_in[0];
    const int*   ids   = (const int*)d_in[1];

    Params P;
    int base = 2;
    for (int m = 0; m < 4; m++) {
        P.W1[m] = (const float*)d_in[base + 0];
        P.b1[m] = (const float*)d_in[base + 1];
        P.W2[m] = (const float*)d_in[base + 2];
        P.b2[m] = (const float*)d_in[base + 3];
        P.te[m] = (const float*)d_in[base + 4];
        base += 5;
    }
    float* out = (float*)d_out;

    k_stage1<<<128, 512>>>(state, ids, P);
    k_stage2<<<dim3(8, 4, 32), 128>>>(P, out);
}